// round 11
// baseline (speedup 1.0000x reference)
#include <cuda_runtime.h>
#include <cstdint>

#define N_NODES 512
#define N_EDGES (512 * 512)
#define CHUNKS 256
#define EDGES_PER_CHUNK (N_EDGES / CHUNKS)   // 1024
#define SPLIT 4
#define NT 128                                // threads per layer CTA

// ---------------- persistent device scratch (no allocations allowed) ---------
__device__ int   g_ptr[N_NODES + 1];
__device__ float g_invc[N_NODES];
__device__ int   g_counts[CHUNKS * N_NODES];
__device__ int   g_base[CHUNKS * N_NODES];
__device__ int   g_srcs[N_EDGES];                       // src, dst-sorted order
__device__ __align__(16) float g_eas[(size_t)N_EDGES * 8];  // ea rows, padded to 32B
__device__ float g_part[N_NODES * SPLIT * 40];          // per-segment partials
__device__ float g_bufA[N_NODES * 36];
__device__ float g_bufB[N_NODES * 36];

// ---------------- f32x2 packed helpers ---------------------------------------
__device__ __forceinline__ uint64_t f2pk(float lo, float hi) {
    uint64_t r; asm("mov.b64 %0, {%1,%2};" : "=l"(r) : "f"(lo), "f"(hi)); return r;
}
__device__ __forceinline__ void f2upk(uint64_t v, float& lo, float& hi) {
    asm("mov.b64 {%0,%1}, %2;" : "=f"(lo), "=f"(hi) : "l"(v));
}
__device__ __forceinline__ uint64_t f2fma(uint64_t a, uint64_t b, uint64_t c) {
    uint64_t d; asm("fma.rn.f32x2 %0, %1, %2, %3;" : "=l"(d) : "l"(a), "l"(b), "l"(c));
    return d;
}
__device__ __forceinline__ uint64_t f2relu(uint64_t v) {
    float lo, hi; f2upk(v, lo, hi);
    return f2pk(fmaxf(lo, 0.f), fmaxf(hi, 0.f));
}

// ---------------- CSR build (atomic-free in gmem) ----------------------------
__global__ __launch_bounds__(256) void count_kernel(const int* __restrict__ dst) {
    __shared__ int h[N_NODES];
    for (int n = threadIdx.x; n < N_NODES; n += 256) h[n] = 0;
    __syncthreads();
    const int base = blockIdx.x * EDGES_PER_CHUNK;
    for (int k = threadIdx.x; k < EDGES_PER_CHUNK; k += 256)
        atomicAdd(&h[dst[base + k]], 1);
    __syncthreads();
    for (int n = threadIdx.x; n < N_NODES; n += 256)
        g_counts[blockIdx.x * N_NODES + n] = h[n];
}

__global__ __launch_bounds__(N_NODES) void plan_kernel() {
    __shared__ int s[N_NODES];
    const int t = threadIdx.x;
    int cnt = 0;
#pragma unroll 4
    for (int c = 0; c < CHUNKS; c++) cnt += g_counts[c * N_NODES + t];
    s[t] = cnt;
    __syncthreads();
    for (int off = 1; off < N_NODES; off <<= 1) {
        int v = (t >= off) ? s[t - off] : 0;
        __syncthreads();
        s[t] += v;
        __syncthreads();
    }
    const int incl = s[t];
    g_ptr[t + 1] = incl;
    if (t == 0) g_ptr[0] = 0;
    g_invc[t] = 1.0f / (float)max(cnt, 1);
    int run = incl - cnt;
#pragma unroll 4
    for (int c = 0; c < CHUNKS; c++) {
        int v = g_counts[c * N_NODES + t];
        g_base[c * N_NODES + t] = run;
        run += v;
    }
}

__global__ __launch_bounds__(256) void scatter_kernel(const int* __restrict__ srcv,
                                                      const int* __restrict__ dst,
                                                      const float* __restrict__ ea) {
    __shared__ int cur[N_NODES];
    for (int n = threadIdx.x; n < N_NODES; n += 256)
        cur[n] = g_base[blockIdx.x * N_NODES + n];
    __syncthreads();
    const int base = blockIdx.x * EDGES_PER_CHUNK;
    for (int k = threadIdx.x; k < EDGES_PER_CHUNK; k += 256) {
        const int e = base + k;
        const int p = atomicAdd(&cur[dst[e]], 1);
        g_srcs[p] = srcv[e];
        const float2* er = (const float2*)(ea + (size_t)e * 6);
        const float2 e0 = __ldg(er + 0), e1 = __ldg(er + 1), e2 = __ldg(er + 2);
        float4* w = (float4*)(g_eas + (size_t)p * 8);
        w[0] = make_float4(e0.x, e0.y, e1.x, e1.y);
        w[1] = make_float4(e2.x, e2.y, 0.f, 0.f);
    }
}

// ---------------- NNConv msg partials: CTA = (dst, 1/4 segment) --------------
// One edge per thread (typical): segment size = deg/4 ~ 128 = NT.
template <int CIN, int COUT, int COUTP>
__global__ __launch_bounds__(NT, 8) void layer_partial(
    const float* __restrict__ We,     // [6, CIN*COUT]
    const float* __restrict__ be,     // [CIN*COUT]
    const float* __restrict__ hin)    // [N, CIN]
{
    static_assert(COUTP % 4 == 0, "pad");
    __shared__ __align__(16) float sWe[6 * CIN * COUTP];
    __shared__ __align__(16) float sBe[CIN * COUTP];
    __shared__ float sacc[COUTP];

    const int tid = threadIdx.x;
    for (int t = tid; t < 6 * CIN * COUTP; t += NT) {
        int vi = t / COUTP, oc = t % COUTP;
        sWe[t] = (oc < COUT) ? We[vi * COUT + oc] : 0.f;
    }
    for (int t = tid; t < CIN * COUTP; t += NT) {
        int oc = t % COUTP;
        sBe[t] = (oc < COUT) ? be[(t / COUTP) * COUT + oc] : 0.f;
    }
    if (tid < COUTP) sacc[tid] = 0.f;
    __syncthreads();

    const int d   = blockIdx.x / SPLIT;
    const int seg = blockIdx.x % SPLIT;
    const int s0 = g_ptr[d], s1 = g_ptr[d + 1];
    const int len = s1 - s0;
    const int lo = s0 + (len * seg) / SPLIT;
    const int hi = s0 + (len * (seg + 1)) / SPLIT;

    uint64_t msg[COUTP / 2];
#pragma unroll
    for (int p = 0; p < COUTP / 2; p++) msg[p] = 0;

    for (int k = lo + tid; k < hi; k += NT) {   // usually exactly 0 or 1 pass
        const float4 e0 = __ldg((const float4*)(g_eas + (size_t)k * 8));
        const float2 e1 = __ldg((const float2*)(g_eas + (size_t)k * 8 + 4));
        uint64_t ap[6];
        ap[0] = f2pk(e0.x, e0.x); ap[1] = f2pk(e0.y, e0.y);
        ap[2] = f2pk(e0.z, e0.z); ap[3] = f2pk(e0.w, e0.w);
        ap[4] = f2pk(e1.x, e1.x); ap[5] = f2pk(e1.y, e1.y);
        const int s = __ldg(g_srcs + k);
        const float* xr = hin + s * CIN;

        auto body = [&](int i, float xi) {
            const uint64_t xip = f2pk(xi, xi);
            const ulonglong2* w0 = (const ulonglong2*)(sWe + (0 * CIN + i) * COUTP);
            const ulonglong2* w1 = (const ulonglong2*)(sWe + (1 * CIN + i) * COUTP);
            const ulonglong2* w2 = (const ulonglong2*)(sWe + (2 * CIN + i) * COUTP);
            const ulonglong2* w3 = (const ulonglong2*)(sWe + (3 * CIN + i) * COUTP);
            const ulonglong2* w4 = (const ulonglong2*)(sWe + (4 * CIN + i) * COUTP);
            const ulonglong2* w5 = (const ulonglong2*)(sWe + (5 * CIN + i) * COUTP);
            const ulonglong2* bb = (const ulonglong2*)(sBe + i * COUTP);
#pragma unroll
            for (int c = 0; c < COUTP / 4; c++) {
                const ulonglong2 bi = bb[c];
                const ulonglong2 q0 = w0[c], q1 = w1[c], q2 = w2[c],
                                 q3 = w3[c], q4 = w4[c], q5 = w5[c];
                uint64_t t0 = f2fma(ap[0], q0.x, bi.x);
                t0 = f2fma(ap[1], q1.x, t0); t0 = f2fma(ap[2], q2.x, t0);
                t0 = f2fma(ap[3], q3.x, t0); t0 = f2fma(ap[4], q4.x, t0);
                t0 = f2fma(ap[5], q5.x, t0);
                uint64_t t1 = f2fma(ap[0], q0.y, bi.y);
                t1 = f2fma(ap[1], q1.y, t1); t1 = f2fma(ap[2], q2.y, t1);
                t1 = f2fma(ap[3], q3.y, t1); t1 = f2fma(ap[4], q4.y, t1);
                t1 = f2fma(ap[5], q5.y, t1);
                t0 = f2relu(t0);
                t1 = f2relu(t1);
                msg[2 * c + 0] = f2fma(xip, t0, msg[2 * c + 0]);
                msg[2 * c + 1] = f2fma(xip, t1, msg[2 * c + 1]);
            }
        };

        if (CIN == 1) {
            body(0, __ldg(xr));
        } else {
            const float4* xr4 = (const float4*)xr;
#pragma unroll 1   // keep 4-i blocks rolled: I$ discipline
            for (int ib = 0; ib < CIN / 4; ib++) {
                const float4 xq = __ldg(xr4 + ib);
                body(4 * ib + 0, xq.x);
                body(4 * ib + 1, xq.y);
                body(4 * ib + 2, xq.z);
                body(4 * ib + 3, xq.w);
            }
        }
    }

    // block reduction: warp shfl -> smem atomics
#pragma unroll
    for (int p = 0; p < COUTP / 2; p++) {
        float lo2, hi2; f2upk(msg[p], lo2, hi2);
#pragma unroll
        for (int sh = 16; sh; sh >>= 1) {
            lo2 += __shfl_down_sync(0xffffffffu, lo2, sh);
            hi2 += __shfl_down_sync(0xffffffffu, hi2, sh);
        }
        if ((tid & 31) == 0) {
            atomicAdd(&sacc[2 * p + 0], lo2);
            atomicAdd(&sacc[2 * p + 1], hi2);
        }
    }
    __syncthreads();

    if (tid < COUTP)
        g_part[(size_t)blockIdx.x * 40 + tid] = sacc[tid];
}

// ---------------- finalize: combine segments + root + bias + relu ------------
template <int CIN, int COUT>
__global__ __launch_bounds__(64) void finalize_kernel(
    const float* __restrict__ root,   // [CIN, COUT]
    const float* __restrict__ bias,   // [COUT]
    const float* __restrict__ hin,    // [N, CIN]
    float*       __restrict__ hout)   // [N, COUT]
{
    const int d = blockIdx.x;
    const int o = threadIdx.x;
    if (o >= COUT) return;
    float s = 0.f;
#pragma unroll
    for (int g = 0; g < SPLIT; g++)
        s += g_part[(size_t)(d * SPLIT + g) * 40 + o];
    float r = bias[o];
#pragma unroll 1
    for (int i = 0; i < CIN; i++)
        r = fmaf(hin[d * CIN + i], root[i * COUT + o], r);
    hout[d * COUT + o] = fmaxf(fmaf(s, g_invc[d], r), 0.f);
}

// ---------------- CBT: out[i][j] = sum_k |h[i][k]-h[j][k]|, k<5 --------------
__global__ __launch_bounds__(256) void cbt_kernel(const float* __restrict__ h,
                                                  float* __restrict__ out) {
    __shared__ float sh[N_NODES * 5];
    for (int t = threadIdx.x; t < N_NODES * 5; t += 256) sh[t] = h[t];
    __syncthreads();
    const int i = blockIdx.x;
    const float h0 = sh[i * 5 + 0], h1 = sh[i * 5 + 1], h2 = sh[i * 5 + 2],
                h3 = sh[i * 5 + 3], h4 = sh[i * 5 + 4];
    for (int j = threadIdx.x; j < N_NODES; j += 256) {
        float s = fabsf(h0 - sh[j * 5 + 0]) + fabsf(h1 - sh[j * 5 + 1]) +
                  fabsf(h2 - sh[j * 5 + 2]) + fabsf(h3 - sh[j * 5 + 3]) +
                  fabsf(h4 - sh[j * 5 + 4]);
        out[i * N_NODES + j] = s;
    }
}

// ---------------- launch ------------------------------------------------------
extern "C" void kernel_launch(void* const* d_in, const int* in_sizes, int n_in,
                              void* d_out, int out_size) {
    const float* x    = (const float*)d_in[0];
    const float* ea   = (const float*)d_in[1];
    const int*   ei   = (const int*)d_in[2];
    const float* We1  = (const float*)d_in[3];
    const float* be1  = (const float*)d_in[4];
    const float* root1= (const float*)d_in[5];
    const float* b1   = (const float*)d_in[6];
    const float* We2  = (const float*)d_in[7];
    const float* be2  = (const float*)d_in[8];
    const float* root2= (const float*)d_in[9];
    const float* b2   = (const float*)d_in[10];
    const float* We3  = (const float*)d_in[11];
    const float* be3  = (const float*)d_in[12];
    const float* root3= (const float*)d_in[13];
    const float* b3   = (const float*)d_in[14];
    float* out = (float*)d_out;

    const int* src = ei;
    const int* dst = ei + N_EDGES;

    float* hA = nullptr;
    float* hB = nullptr;
    cudaGetSymbolAddress((void**)&hA, g_bufA);
    cudaGetSymbolAddress((void**)&hB, g_bufB);

    // CSR build + edge-data permute into dst-sorted order
    count_kernel<<<CHUNKS, 256>>>(dst);
    plan_kernel<<<1, N_NODES>>>();
    scatter_kernel<<<CHUNKS, 256>>>(src, dst, ea);

    // layer 1: 1 -> 36
    layer_partial<1, 36, 36><<<N_NODES * SPLIT, NT>>>(We1, be1, x);
    finalize_kernel<1, 36><<<N_NODES, 64>>>(root1, b1, x, hA);

    // layer 2: 36 -> 24
    layer_partial<36, 24, 24><<<N_NODES * SPLIT, NT>>>(We2, be2, hA);
    finalize_kernel<36, 24><<<N_NODES, 64>>>(root2, b2, hA, hB);

    // layer 3: 24 -> 5 (pad 8)
    layer_partial<24, 5, 8><<<N_NODES * SPLIT, NT>>>(We3, be3, hB);
    finalize_kernel<24, 5><<<N_NODES, 64>>>(root3, b3, hB, hA);

    cbt_kernel<<<N_NODES, 256>>>(hA, out);
}

// round 16
// speedup vs baseline: 1.2653x; 1.2653x over previous
#include <cuda_runtime.h>
#include <cstdint>

#define N_NODES 512
#define N_EDGES (512 * 512)
#define CHUNKS 256
#define EDGES_PER_CHUNK (N_EDGES / CHUNKS)   // 1024
#define NT 128

// ---------------- persistent device scratch (no allocations allowed) ---------
__device__ int   g_ptr[N_NODES + 1];
__device__ float g_invc[N_NODES];
__device__ int   g_counts[CHUNKS * N_NODES];
__device__ int   g_base[CHUNKS * N_NODES];
__device__ __align__(16) float g_eas[(size_t)N_EDGES * 8];  // [ea0..5, src_bits, 0]
__device__ float g_bufA[N_NODES * 36];
__device__ float g_bufB[N_NODES * 36];

// ---------------- f32x2 packed helpers ---------------------------------------
__device__ __forceinline__ uint64_t f2pk(float lo, float hi) {
    uint64_t r; asm("mov.b64 %0, {%1,%2};" : "=l"(r) : "f"(lo), "f"(hi)); return r;
}
__device__ __forceinline__ void f2upk(uint64_t v, float& lo, float& hi) {
    asm("mov.b64 {%0,%1}, %2;" : "=f"(lo), "=f"(hi) : "l"(v));
}
__device__ __forceinline__ uint64_t f2fma(uint64_t a, uint64_t b, uint64_t c) {
    uint64_t d; asm("fma.rn.f32x2 %0, %1, %2, %3;" : "=l"(d) : "l"(a), "l"(b), "l"(c));
    return d;
}
__device__ __forceinline__ uint64_t f2relu(uint64_t v) {
    float lo, hi; f2upk(v, lo, hi);
    return f2pk(fmaxf(lo, 0.f), fmaxf(hi, 0.f));
}

// ---------------- CSR build (atomic-free in gmem) ----------------------------
__global__ __launch_bounds__(256) void count_kernel(const int* __restrict__ dst) {
    __shared__ int h[N_NODES];
    for (int n = threadIdx.x; n < N_NODES; n += 256) h[n] = 0;
    __syncthreads();
    const int base = blockIdx.x * EDGES_PER_CHUNK;
    for (int k = threadIdx.x; k < EDGES_PER_CHUNK; k += 256)
        atomicAdd(&h[dst[base + k]], 1);
    __syncthreads();
    for (int n = threadIdx.x; n < N_NODES; n += 256)
        g_counts[blockIdx.x * N_NODES + n] = h[n];
}

__global__ __launch_bounds__(N_NODES) void plan_kernel() {
    __shared__ int s[N_NODES];
    const int t = threadIdx.x;
    int cnt = 0;
#pragma unroll 4
    for (int c = 0; c < CHUNKS; c++) cnt += g_counts[c * N_NODES + t];
    s[t] = cnt;
    __syncthreads();
    for (int off = 1; off < N_NODES; off <<= 1) {
        int v = (t >= off) ? s[t - off] : 0;
        __syncthreads();
        s[t] += v;
        __syncthreads();
    }
    const int incl = s[t];
    g_ptr[t + 1] = incl;
    if (t == 0) g_ptr[0] = 0;
    g_invc[t] = 1.0f / (float)max(cnt, 1);
    int run = incl - cnt;
#pragma unroll 4
    for (int c = 0; c < CHUNKS; c++) {
        int v = g_counts[c * N_NODES + t];
        g_base[c * N_NODES + t] = run;
        run += v;
    }
}

__global__ __launch_bounds__(256) void scatter_kernel(const int* __restrict__ srcv,
                                                      const int* __restrict__ dst,
                                                      const float* __restrict__ ea) {
    __shared__ int cur[N_NODES];
    for (int n = threadIdx.x; n < N_NODES; n += 256)
        cur[n] = g_base[blockIdx.x * N_NODES + n];
    __syncthreads();
    const int base = blockIdx.x * EDGES_PER_CHUNK;
    for (int k = threadIdx.x; k < EDGES_PER_CHUNK; k += 256) {
        const int e = base + k;
        const int p = atomicAdd(&cur[dst[e]], 1);
        const float2* er = (const float2*)(ea + (size_t)e * 6);
        const float2 e0 = __ldg(er + 0), e1 = __ldg(er + 1), e2 = __ldg(er + 2);
        float4* w = (float4*)(g_eas + (size_t)p * 8);
        w[0] = make_float4(e0.x, e0.y, e1.x, e1.y);
        w[1] = make_float4(e2.x, e2.y, __int_as_float(srcv[e]), 0.f);
    }
}

// ---------------- fused NNConv layer slice, EB2 ------------------------------
// CTA = (dst d, channel slice). Thread handles edge pair (k, k+NT), sharing
// every weight LDS between the two edges. Slice finalizes its own hout cols.
template <int CIN, int COUT, int SLICE, int SLICEP>
__global__ __launch_bounds__(NT) void layer_slice(
    const float* __restrict__ We,     // [6, CIN*COUT]
    const float* __restrict__ be,     // [CIN*COUT]
    const float* __restrict__ root,   // [CIN, COUT]
    const float* __restrict__ bias,   // [COUT]
    const float* __restrict__ hin,    // [N, CIN]
    float*       __restrict__ hout)   // [N, COUT]
{
    static_assert(SLICEP % 4 == 0, "pad");
    __shared__ __align__(16) float sWe[6 * CIN * SLICEP];
    __shared__ __align__(16) float sBe[CIN * SLICEP];
    __shared__ float sacc[SLICEP];

    const int tid  = threadIdx.x;
    const int coff = blockIdx.y * SLICE;

    for (int t = tid; t < 6 * CIN * SLICEP; t += NT) {
        int vi = t / SLICEP, oc = t % SLICEP;
        sWe[t] = (oc < SLICE) ? We[vi * COUT + coff + oc] : 0.f;
    }
    for (int t = tid; t < CIN * SLICEP; t += NT) {
        int oc = t % SLICEP;
        sBe[t] = (oc < SLICE) ? be[(t / SLICEP) * COUT + coff + oc] : 0.f;
    }
    if (tid < SLICEP) sacc[tid] = 0.f;
    __syncthreads();

    const int d = blockIdx.x;
    const int start = g_ptr[d], finish = g_ptr[d + 1];

    uint64_t msgA[SLICEP / 2], msgB[SLICEP / 2];
#pragma unroll
    for (int p = 0; p < SLICEP / 2; p++) { msgA[p] = 0; msgB[p] = 0; }

    for (int k0 = start; k0 < finish; k0 += 2 * NT) {
        const int kA = k0 + tid;
        const int kB = kA + NT;
        const bool vA = (kA < finish);
        const bool vB = (kB < finish);
        // clamped indices stay in-bounds; invalid lanes are killed via x=0
        const int iA = vA ? kA : start;
        const int iB = vB ? kB : start;

        const float4 a0 = __ldg((const float4*)(g_eas + (size_t)iA * 8));
        const float4 a1 = __ldg((const float4*)(g_eas + (size_t)iA * 8 + 4));
        const float4 b0 = __ldg((const float4*)(g_eas + (size_t)iB * 8));
        const float4 b1 = __ldg((const float4*)(g_eas + (size_t)iB * 8 + 4));

        uint64_t apA[6], apB[6];
        apA[0] = f2pk(a0.x, a0.x); apA[1] = f2pk(a0.y, a0.y);
        apA[2] = f2pk(a0.z, a0.z); apA[3] = f2pk(a0.w, a0.w);
        apA[4] = f2pk(a1.x, a1.x); apA[5] = f2pk(a1.y, a1.y);
        apB[0] = f2pk(b0.x, b0.x); apB[1] = f2pk(b0.y, b0.y);
        apB[2] = f2pk(b0.z, b0.z); apB[3] = f2pk(b0.w, b0.w);
        apB[4] = f2pk(b1.x, b1.x); apB[5] = f2pk(b1.y, b1.y);

        const int sA = __float_as_int(a1.z);
        const int sB = __float_as_int(b1.z);
        const float* xrA = hin + sA * CIN;
        const float* xrB = hin + sB * CIN;

        auto body = [&](int i, float xiA, float xiB) {
            const uint64_t xpA = f2pk(xiA, xiA);
            const uint64_t xpB = f2pk(xiB, xiB);
            const ulonglong2* w0 = (const ulonglong2*)(sWe + (0 * CIN + i) * SLICEP);
            const ulonglong2* w1 = (const ulonglong2*)(sWe + (1 * CIN + i) * SLICEP);
            const ulonglong2* w2 = (const ulonglong2*)(sWe + (2 * CIN + i) * SLICEP);
            const ulonglong2* w3 = (const ulonglong2*)(sWe + (3 * CIN + i) * SLICEP);
            const ulonglong2* w4 = (const ulonglong2*)(sWe + (4 * CIN + i) * SLICEP);
            const ulonglong2* w5 = (const ulonglong2*)(sWe + (5 * CIN + i) * SLICEP);
            const ulonglong2* bb = (const ulonglong2*)(sBe + i * SLICEP);
#pragma unroll
            for (int c = 0; c < SLICEP / 4; c++) {
                const ulonglong2 bi = bb[c];
                const ulonglong2 q0 = w0[c], q1 = w1[c], q2 = w2[c],
                                 q3 = w3[c], q4 = w4[c], q5 = w5[c];
                uint64_t tA0 = f2fma(apA[0], q0.x, bi.x);
                tA0 = f2fma(apA[1], q1.x, tA0); tA0 = f2fma(apA[2], q2.x, tA0);
                tA0 = f2fma(apA[3], q3.x, tA0); tA0 = f2fma(apA[4], q4.x, tA0);
                tA0 = f2fma(apA[5], q5.x, tA0);
                uint64_t tB0 = f2fma(apB[0], q0.x, bi.x);
                tB0 = f2fma(apB[1], q1.x, tB0); tB0 = f2fma(apB[2], q2.x, tB0);
                tB0 = f2fma(apB[3], q3.x, tB0); tB0 = f2fma(apB[4], q4.x, tB0);
                tB0 = f2fma(apB[5], q5.x, tB0);
                uint64_t tA1 = f2fma(apA[0], q0.y, bi.y);
                tA1 = f2fma(apA[1], q1.y, tA1); tA1 = f2fma(apA[2], q2.y, tA1);
                tA1 = f2fma(apA[3], q3.y, tA1); tA1 = f2fma(apA[4], q4.y, tA1);
                tA1 = f2fma(apA[5], q5.y, tA1);
                uint64_t tB1 = f2fma(apB[0], q0.y, bi.y);
                tB1 = f2fma(apB[1], q1.y, tB1); tB1 = f2fma(apB[2], q2.y, tB1);
                tB1 = f2fma(apB[3], q3.y, tB1); tB1 = f2fma(apB[4], q4.y, tB1);
                tB1 = f2fma(apB[5], q5.y, tB1);
                tA0 = f2relu(tA0); tB0 = f2relu(tB0);
                tA1 = f2relu(tA1); tB1 = f2relu(tB1);
                msgA[2 * c + 0] = f2fma(xpA, tA0, msgA[2 * c + 0]);
                msgA[2 * c + 1] = f2fma(xpA, tA1, msgA[2 * c + 1]);
                msgB[2 * c + 0] = f2fma(xpB, tB0, msgB[2 * c + 0]);
                msgB[2 * c + 1] = f2fma(xpB, tB1, msgB[2 * c + 1]);
            }
        };

        if (CIN == 1) {
            const float xiA = vA ? __ldg(xrA) : 0.f;   // x=0 kills invalid lane
            const float xiB = vB ? __ldg(xrB) : 0.f;
            body(0, xiA, xiB);
        } else {
            const float4* xA4 = (const float4*)xrA;
            const float4* xB4 = (const float4*)xrB;
#pragma unroll 1   // keep 4-i blocks rolled: I$ discipline
            for (int ib = 0; ib < CIN / 4; ib++) {
                float4 xqA = make_float4(0.f, 0.f, 0.f, 0.f);
                float4 xqB = make_float4(0.f, 0.f, 0.f, 0.f);
                if (vA) xqA = __ldg(xA4 + ib);
                if (vB) xqB = __ldg(xB4 + ib);
                body(4 * ib + 0, xqA.x, xqB.x);
                body(4 * ib + 1, xqA.y, xqB.y);
                body(4 * ib + 2, xqA.z, xqB.z);
                body(4 * ib + 3, xqA.w, xqB.w);
            }
        }
    }

    // fold pair accumulators, then block reduction (4 warps)
#pragma unroll
    for (int p = 0; p < SLICEP / 2; p++) {
        float loA, hiA, loB, hiB;
        f2upk(msgA[p], loA, hiA); f2upk(msgB[p], loB, hiB);
        float lo = loA + loB, hi = hiA + hiB;
#pragma unroll
        for (int sh = 16; sh; sh >>= 1) {
            lo += __shfl_down_sync(0xffffffffu, lo, sh);
            hi += __shfl_down_sync(0xffffffffu, hi, sh);
        }
        if ((tid & 31) == 0) {
            atomicAdd(&sacc[2 * p + 0], lo);
            atomicAdd(&sacc[2 * p + 1], hi);
        }
    }
    __syncthreads();

    // finalize this slice's output columns directly
    if (tid < SLICE) {
        const int o = coff + tid;
        float r = bias[o];
#pragma unroll 1
        for (int i = 0; i < CIN; i++)
            r = fmaf(hin[d * CIN + i], root[i * COUT + o], r);
        hout[d * COUT + o] = fmaxf(fmaf(sacc[tid], g_invc[d], r), 0.f);
    }
}

// ---------------- CBT: out[i][j] = sum_k |h[i][k]-h[j][k]|, k<5 --------------
__global__ __launch_bounds__(256) void cbt_kernel(const float* __restrict__ h,
                                                  float* __restrict__ out) {
    __shared__ float sh[N_NODES * 5];
    for (int t = threadIdx.x; t < N_NODES * 5; t += 256) sh[t] = h[t];
    __syncthreads();
    const int i = blockIdx.x;
    const float h0 = sh[i * 5 + 0], h1 = sh[i * 5 + 1], h2 = sh[i * 5 + 2],
                h3 = sh[i * 5 + 3], h4 = sh[i * 5 + 4];
    for (int j = threadIdx.x; j < N_NODES; j += 256) {
        float s = fabsf(h0 - sh[j * 5 + 0]) + fabsf(h1 - sh[j * 5 + 1]) +
                  fabsf(h2 - sh[j * 5 + 2]) + fabsf(h3 - sh[j * 5 + 3]) +
                  fabsf(h4 - sh[j * 5 + 4]);
        out[i * N_NODES + j] = s;
    }
}

// ---------------- launch ------------------------------------------------------
extern "C" void kernel_launch(void* const* d_in, const int* in_sizes, int n_in,
                              void* d_out, int out_size) {
    const float* x    = (const float*)d_in[0];
    const float* ea   = (const float*)d_in[1];
    const int*   ei   = (const int*)d_in[2];
    const float* We1  = (const float*)d_in[3];
    const float* be1  = (const float*)d_in[4];
    const float* root1= (const float*)d_in[5];
    const float* b1   = (const float*)d_in[6];
    const float* We2  = (const float*)d_in[7];
    const float* be2  = (const float*)d_in[8];
    const float* root2= (const float*)d_in[9];
    const float* b2   = (const float*)d_in[10];
    const float* We3  = (const float*)d_in[11];
    const float* be3  = (const float*)d_in[12];
    const float* root3= (const float*)d_in[13];
    const float* b3   = (const float*)d_in[14];
    float* out = (float*)d_out;

    const int* src = ei;
    const int* dst = ei + N_EDGES;

    float* hA = nullptr;
    float* hB = nullptr;
    cudaGetSymbolAddress((void**)&hA, g_bufA);
    cudaGetSymbolAddress((void**)&hB, g_bufB);

    // CSR build + edge-data permute (src folded into the padded ea row)
    count_kernel<<<CHUNKS, 256>>>(dst);
    plan_kernel<<<1, N_NODES>>>();
    scatter_kernel<<<CHUNKS, 256>>>(src, dst, ea);

    // layer 1: 1 -> 36, 2 slices of 18 (pad 20)
    layer_slice<1, 36, 18, 20><<<dim3(N_NODES, 2), NT>>>(We1, be1, root1, b1, x, hA);
    // layer 2: 36 -> 24, 2 slices of 12
    layer_slice<36, 24, 12, 12><<<dim3(N_NODES, 2), NT>>>(We2, be2, root2, b2, hA, hB);
    // layer 3: 24 -> 5 (pad 8), unsplit
    layer_slice<24, 5, 5, 8><<<dim3(N_NODES, 1), NT>>>(We3, be3, root3, b3, hB, hA);

    cbt_kernel<<<N_NODES, 256>>>(hA, out);
}